// round 13
// baseline (speedup 1.0000x reference)
#include <cuda_runtime.h>
#include <cuda_bf16.h>
#include <math.h>
#include <stdint.h>

// ---------------- problem constants ----------------
#define SEQ     2048
#define BATCH   2
#define DMODEL  2048
#define NHEADS  16
#define DH      128
#define NOPE    64
#define ROPE_D  64
#define QPROJ   1024
#define KVPROJ  1365
#define CKV_COLS 1429          // KVPROJ + ROPE_D
#define KVOUT   3072           // NHEADS * (DH + NOPE)
#define MROWS   (BATCH*SEQ)    // 4096
#define KVHEAD  192            // DH + NOPE per head in KV
#define KVL_PAD 1376           // KVPROJ padded to a multiple of 32
#define WDKV_ROWS 1536         // CKV_COLS padded to a multiple of 128

// ---------------- fp32 scratch ----------------
__device__ float g_cq[(size_t)MROWS*QPROJ];
__device__ float g_Q[(size_t)MROWS*DMODEL];
__device__ float g_KV[(size_t)MROWS*KVOUT];
__device__ float g_Krope[(size_t)MROWS*ROPE_D];

// ---------------- bf16 hi/lo operand buffers (pre-split) ----------------
__device__ __align__(16) __nv_bfloat16 g_xH  [(size_t)MROWS*DMODEL];
__device__ __align__(16) __nv_bfloat16 g_xL  [(size_t)MROWS*DMODEL];
__device__ __align__(16) __nv_bfloat16 g_cqH [(size_t)MROWS*QPROJ];
__device__ __align__(16) __nv_bfloat16 g_cqL [(size_t)MROWS*QPROJ];
__device__ __align__(16) __nv_bfloat16 g_kvlH[(size_t)MROWS*KVL_PAD];
__device__ __align__(16) __nv_bfloat16 g_kvlL[(size_t)MROWS*KVL_PAD];
__device__ __align__(16) __nv_bfloat16 g_aoH [(size_t)MROWS*DMODEL];
__device__ __align__(16) __nv_bfloat16 g_aoL [(size_t)MROWS*DMODEL];
__device__ __align__(16) __nv_bfloat16 g_WdqH [(size_t)QPROJ*DMODEL];
__device__ __align__(16) __nv_bfloat16 g_WdqL [(size_t)QPROJ*DMODEL];
__device__ __align__(16) __nv_bfloat16 g_WuqH [(size_t)DMODEL*QPROJ];
__device__ __align__(16) __nv_bfloat16 g_WuqL [(size_t)DMODEL*QPROJ];
__device__ __align__(16) __nv_bfloat16 g_WdkvH[(size_t)WDKV_ROWS*DMODEL];
__device__ __align__(16) __nv_bfloat16 g_WdkvL[(size_t)WDKV_ROWS*DMODEL];
__device__ __align__(16) __nv_bfloat16 g_WukvH[(size_t)KVOUT*KVL_PAD];
__device__ __align__(16) __nv_bfloat16 g_WukvL[(size_t)KVOUT*KVL_PAD];
__device__ __align__(16) __nv_bfloat16 g_WoH  [(size_t)DMODEL*DMODEL];
__device__ __align__(16) __nv_bfloat16 g_WoL  [(size_t)DMODEL*DMODEL];

// fp32 buffer selectors
#define BUF_CQ 0
#define BUF_Q  1
#define BUF_KV 2
__device__ __forceinline__ float* sel_f(int s) {
    switch (s) { case BUF_CQ: return g_cq; case BUF_Q: return g_Q; default: return g_KV; }
}
// bf16 buffer selectors
#define BB_XH 0
#define BB_XL 1
#define BB_CQH 2
#define BB_CQL 3
#define BB_KVLH 4
#define BB_KVLL 5
#define BB_AOH 6
#define BB_AOL 7
#define BB_WDQH 8
#define BB_WDQL 9
#define BB_WUQH 10
#define BB_WUQL 11
#define BB_WDKVH 12
#define BB_WDKVL 13
#define BB_WUKVH 14
#define BB_WUKVL 15
#define BB_WOH 16
#define BB_WOL 17
__device__ __forceinline__ __nv_bfloat16* sel_b(int s) {
    switch (s) {
        case BB_XH: return g_xH;       case BB_XL: return g_xL;
        case BB_CQH: return g_cqH;     case BB_CQL: return g_cqL;
        case BB_KVLH: return g_kvlH;   case BB_KVLL: return g_kvlL;
        case BB_AOH: return g_aoH;     case BB_AOL: return g_aoL;
        case BB_WDQH: return g_WdqH;   case BB_WDQL: return g_WdqL;
        case BB_WUQH: return g_WuqH;   case BB_WUQL: return g_WuqL;
        case BB_WDKVH: return g_WdkvH; case BB_WDKVL: return g_WdkvL;
        case BB_WUKVH: return g_WukvH; case BB_WUKVL: return g_WukvL;
        case BB_WOH: return g_WoH;     default: return g_WoL;
    }
}

__device__ __forceinline__ void split_bf16(float v, __nv_bfloat16& h, __nv_bfloat16& l)
{
    h = __float2bfloat16(v);
    l = __float2bfloat16(v - __bfloat162float(h));
}

// =====================================================================
// transpose_split: in fp32 [K][N] -> out hi/lo bf16 [Npad][Kpad], zero pad.
// grid (ceil(Npad/32), ceil(Kpad/32)), block (32, 8).
// =====================================================================
__global__ __launch_bounds__(256)
void transpose_split(const float* __restrict__ in, int selH, int selL,
                     int K, int N, int Kpad, int Npad)
{
    __shared__ float t[32][33];
    __nv_bfloat16* outH = sel_b(selH);
    __nv_bfloat16* outL = sel_b(selL);
    int x  = blockIdx.x * 32 + threadIdx.x;   // n
    int y0 = blockIdx.y * 32;                 // k base
#pragma unroll
    for (int j = threadIdx.y; j < 32; j += 8)
        t[j][threadIdx.x] = (x < N && y0 + j < K) ? in[(size_t)(y0 + j) * N + x] : 0.f;
    __syncthreads();
    int x2 = blockIdx.y * 32 + threadIdx.x;   // k
    int y2 = blockIdx.x * 32;                 // n base
#pragma unroll
    for (int j = threadIdx.y; j < 32; j += 8)
        if (x2 < Kpad && y2 + j < Npad) {
            __nv_bfloat16 h, l;
            split_bf16(t[threadIdx.x][j], h, l);
            outH[(size_t)(y2 + j) * Kpad + x2] = h;
            outL[(size_t)(y2 + j) * Kpad + x2] = l;
        }
}

// =====================================================================
// split_rows: fp32 [R][C] -> hi/lo bf16 [R][Cpad], zero pad cols.
// =====================================================================
__global__ __launch_bounds__(256)
void split_rows(const float* __restrict__ in, int selH, int selL,
                int R, int C, int Cpad)
{
    __nv_bfloat16* outH = sel_b(selH);
    __nv_bfloat16* outL = sel_b(selL);
    size_t total = (size_t)R * Cpad;
    for (size_t i = (size_t)blockIdx.x * blockDim.x + threadIdx.x; i < total;
         i += (size_t)gridDim.x * blockDim.x) {
        size_t r = i / Cpad;
        int    c = (int)(i - r * Cpad);
        float v = (c < C) ? in[r * C + c] : 0.f;
        __nv_bfloat16 h, l;
        split_bf16(v, h, l);
        outH[i] = h; outL[i] = l;
    }
}

// =====================================================================
// Pre-split bf16x3 tensor-core GEMM (NT): C = A @ Bt^T, fp32 accum.
// Operands are bf16 hi/lo pairs in gmem, K % 32 == 0, rows padded so
// loads need NO guards. 128x128x32 tile, 8 warps, mma.m16n8k16.
// =====================================================================
#define PADK 40   // smem row stride in bf16 elements

__device__ __forceinline__ void mma_bf16(float* c, const uint32_t* a, const uint32_t* b)
{
    asm volatile(
        "mma.sync.aligned.m16n8k16.row.col.f32.bf16.bf16.f32 "
        "{%0,%1,%2,%3}, {%4,%5,%6,%7}, {%8,%9}, {%0,%1,%2,%3};\n"
        : "+f"(c[0]), "+f"(c[1]), "+f"(c[2]), "+f"(c[3])
        : "r"(a[0]), "r"(a[1]), "r"(a[2]), "r"(a[3]), "r"(b[0]), "r"(b[1]));
}

__global__ __launch_bounds__(256)
void gemm_pre(int aH, int aL, int bH, int bL,
              float* __restrict__ Cext, int cSel, int M, int N, int K)
{
    const __nv_bfloat16* __restrict__ AHi = sel_b(aH);
    const __nv_bfloat16* __restrict__ ALo = sel_b(aL);
    const __nv_bfloat16* __restrict__ BHi = sel_b(bH);
    const __nv_bfloat16* __restrict__ BLo = sel_b(bL);
    float* __restrict__ C = (cSel >= 0) ? sel_f(cSel) : Cext;

    __shared__ __align__(16) __nv_bfloat16 AsHi[128 * PADK];
    __shared__ __align__(16) __nv_bfloat16 AsLo[128 * PADK];
    __shared__ __align__(16) __nv_bfloat16 BsHi[128 * PADK];
    __shared__ __align__(16) __nv_bfloat16 BsLo[128 * PADK];

    const int tid  = threadIdx.x;
    const int lane = tid & 31;
    const int warp = tid >> 5;
    const int g    = lane >> 2;
    const int tig  = lane & 3;
    const int wm   = (warp & 1) * 64;
    const int wn   = (warp >> 1) * 32;
    const int m0   = blockIdx.y * 128;
    const int n0   = blockIdx.x * 128;

    float acc[4][4][4];
#pragma unroll
    for (int mt = 0; mt < 4; mt++)
#pragma unroll
        for (int nt = 0; nt < 4; nt++)
#pragma unroll
            for (int i = 0; i < 4; i++) acc[mt][nt][i] = 0.f;

    const int nk = K >> 5;

    // per k-tile, per array: 128 rows x 32 halves = 512 x 16B chunks; 2/thread
    uint4 vAH[2], vAL[2], vBH[2], vBL[2];

    auto loadTile = [&](int kt) {
        const int k0 = kt << 5;
#pragma unroll
        for (int p = 0; p < 2; p++) {
            int lin = tid + p * 256;
            int r = lin >> 2, c8 = (lin & 3) << 3;
            size_t offA = (size_t)(m0 + r) * K + k0 + c8;
            size_t offB = (size_t)(n0 + r) * K + k0 + c8;
            vAH[p] = *(const uint4*)&AHi[offA];
            vAL[p] = *(const uint4*)&ALo[offA];
            vBH[p] = *(const uint4*)&BHi[offB];
            vBL[p] = *(const uint4*)&BLo[offB];
        }
    };

    auto storeTile = [&]() {
#pragma unroll
        for (int p = 0; p < 2; p++) {
            int lin = tid + p * 256;
            int r = lin >> 2, c8 = (lin & 3) << 3;
            int off = r * PADK + c8;       // byte offset r*80 + c8*2 -> 16B aligned
            *(uint4*)&AsHi[off] = vAH[p];
            *(uint4*)&AsLo[off] = vAL[p];
            *(uint4*)&BsHi[off] = vBH[p];
            *(uint4*)&BsLo[off] = vBL[p];
        }
    };

    loadTile(0);
    for (int kt = 0; kt < nk; kt++) {
        storeTile();
        __syncthreads();
        if (kt + 1 < nk) loadTile(kt + 1);   // overlap next-tile LDGs with MMA

#pragma unroll
        for (int kk = 0; kk < 32; kk += 16) {
            uint32_t aHi[4][4], aLo[4][4], bHi[4][2], bLo[4][2];
#pragma unroll
            for (int mt = 0; mt < 4; mt++) {
                int rA = (wm + mt * 16 + g) * PADK + kk + 2 * tig;
                aHi[mt][0] = *(const uint32_t*)&AsHi[rA];
                aHi[mt][1] = *(const uint32_t*)&AsHi[rA + 8 * PADK];
                aHi[mt][2] = *(const uint32_t*)&AsHi[rA + 8];
                aHi[mt][3] = *(const uint32_t*)&AsHi[rA + 8 * PADK + 8];
                aLo[mt][0] = *(const uint32_t*)&AsLo[rA];
                aLo[mt][1] = *(const uint32_t*)&AsLo[rA + 8 * PADK];
                aLo[mt][2] = *(const uint32_t*)&AsLo[rA + 8];
                aLo[mt][3] = *(const uint32_t*)&AsLo[rA + 8 * PADK + 8];
            }
#pragma unroll
            for (int nt = 0; nt < 4; nt++) {
                int rB = (wn + nt * 8 + g) * PADK + kk + 2 * tig;
                bHi[nt][0] = *(const uint32_t*)&BsHi[rB];
                bHi[nt][1] = *(const uint32_t*)&BsHi[rB + 8];
                bLo[nt][0] = *(const uint32_t*)&BsLo[rB];
                bLo[nt][1] = *(const uint32_t*)&BsLo[rB + 8];
            }
#pragma unroll
            for (int mt = 0; mt < 4; mt++)
#pragma unroll
                for (int nt = 0; nt < 4; nt++) {
                    mma_bf16(acc[mt][nt], aHi[mt], bHi[nt]);
                    mma_bf16(acc[mt][nt], aHi[mt], bLo[nt]);
                    mma_bf16(acc[mt][nt], aLo[mt], bHi[nt]);
                }
        }
        __syncthreads();
    }

    if ((N & 1) == 0) {
#pragma unroll
        for (int mt = 0; mt < 4; mt++)
#pragma unroll
            for (int nt = 0; nt < 4; nt++) {
                int r = m0 + wm + mt * 16 + g;
                int c = n0 + wn + nt * 8 + 2 * tig;
                *(float2*)&C[(size_t)r * N + c] =
                    make_float2(acc[mt][nt][0], acc[mt][nt][1]);
                *(float2*)&C[(size_t)(r + 8) * N + c] =
                    make_float2(acc[mt][nt][2], acc[mt][nt][3]);
            }
    } else {   // odd N (1429): scalar guarded stores
#pragma unroll
        for (int mt = 0; mt < 4; mt++)
#pragma unroll
            for (int nt = 0; nt < 4; nt++) {
                int r = m0 + wm + mt * 16 + g;
                int c = n0 + wn + nt * 8 + 2 * tig;
                if (c < N)     C[(size_t)r * N + c]           = acc[mt][nt][0];
                if (c + 1 < N) C[(size_t)r * N + c + 1]       = acc[mt][nt][1];
                if (c < N)     C[(size_t)(r + 8) * N + c]     = acc[mt][nt][2];
                if (c + 1 < N) C[(size_t)(r + 8) * N + c + 1] = acc[mt][nt][3];
            }
    }
}

// =====================================================================
// LayerNorm that writes a bf16 hi/lo pair (zero-pads cols to colsPad).
// One block (256 thr) per row.
// =====================================================================
__global__ __launch_bounds__(256)
void ln_split(const float* __restrict__ inExt, int inSel,
              int selH, int selL,
              const float* __restrict__ w, const float* __restrict__ b,
              int cols, int in_stride, int colsPad)
{
    const float* in = (inSel >= 0) ? sel_f(inSel) : inExt;
    __nv_bfloat16* outH = sel_b(selH);
    __nv_bfloat16* outL = sel_b(selL);

    __shared__ float rs[32], rs2[32];
    const size_t row = blockIdx.x;
    const float* x = in + row * (size_t)in_stride;

    float s = 0.f, s2 = 0.f;
    for (int c = threadIdx.x; c < cols; c += blockDim.x) {
        float v = x[c]; s += v; s2 += v * v;
    }
#pragma unroll
    for (int o = 16; o; o >>= 1) {
        s  += __shfl_xor_sync(0xffffffffu, s,  o);
        s2 += __shfl_xor_sync(0xffffffffu, s2, o);
    }
    int lane = threadIdx.x & 31, wid = threadIdx.x >> 5;
    if (lane == 0) { rs[wid] = s; rs2[wid] = s2; }
    __syncthreads();
    if (wid == 0) {
        int nw = blockDim.x >> 5;
        s  = (lane < nw) ? rs[lane]  : 0.f;
        s2 = (lane < nw) ? rs2[lane] : 0.f;
#pragma unroll
        for (int o = 16; o; o >>= 1) {
            s  += __shfl_xor_sync(0xffffffffu, s,  o);
            s2 += __shfl_xor_sync(0xffffffffu, s2, o);
        }
        if (lane == 0) { rs[0] = s; rs2[0] = s2; }
    }
    __syncthreads();
    float mean = rs[0] / (float)cols;
    float var  = rs2[0] / (float)cols - mean * mean;
    float inv  = rsqrtf(var + 1e-5f);
    for (int c = threadIdx.x; c < colsPad; c += blockDim.x) {
        float y = (c < cols) ? (x[c] - mean) * inv * w[c] + b[c] : 0.f;
        __nv_bfloat16 h, l;
        split_bf16(y, h, l);
        outH[row * (size_t)colsPad + c] = h;
        outL[row * (size_t)colsPad + c] = l;
    }
}

// =====================================================================
// RoPE on Q (g_Q, in place). 512 thr = 16 heads x 32 lanes; block per (b,s).
// =====================================================================
__global__ __launch_bounds__(512)
void rope_q_kernel()
{
    int bs = blockIdx.x;
    int s  = bs & (SEQ - 1);
    int h  = threadIdx.x >> 5;
    int j  = threadIdx.x & 31;
    double f   = pow(10000.0, -(double)j / 64.0);
    double ang = (double)s * f;
    double cd, sd; sincos(ang, &sd, &cd);
    float c = (float)cd, sn = (float)sd;
    float* q = g_Q + (size_t)bs * DMODEL + h * DH + NOPE;
    float x1 = q[j], x2 = q[j + 32];
    q[j]      = x1 * c - x2 * sn;
    q[j + 32] = x2 * c + x1 * sn;
}

// RoPE on K_rope: ckv[:, 1365:1429] -> g_Krope
__global__ __launch_bounds__(32)
void rope_k_kernel(const float* __restrict__ ckv)
{
    int bs = blockIdx.x;
    int s  = bs & (SEQ - 1);
    int j  = threadIdx.x;
    double f   = pow(10000.0, -(double)j / 64.0);
    double ang = (double)s * f;
    double cd, sd; sincos(ang, &sd, &cd);
    float c = (float)cd, sn = (float)sd;
    const float* src = ckv + (size_t)bs * CKV_COLS + KVPROJ;
    float x1 = src[j], x2 = src[j + 32];
    float* dst = g_Krope + (size_t)bs * ROPE_D;
    dst[j]      = x1 * c - x2 * sn;
    dst[j + 32] = x2 * c + x1 * sn;
}

// =====================================================================
// Flash attention (causal). BM=BN=64, dh=128. Epilogue writes hi/lo bf16
// attn_out directly (feeds the final GEMM).
// =====================================================================
#define FL_KSTR 136
#define FLASH_SMEM ((64*128 + 64*FL_KSTR + 64*FL_KSTR + 64*64) * 4)

__global__ __launch_bounds__(256)
void flash_kernel()
{
    extern __shared__ float sm[];
    float* Qs = sm;
    float* Ks = Qs + 64*128;
    float* Vs = Ks + 64*FL_KSTR;
    float* Ps = Vs + 64*FL_KSTR;

    const float* __restrict__ Q     = g_Q;
    const float* __restrict__ KV    = g_KV;
    const float* __restrict__ Krope = g_Krope;

    const int q0 = blockIdx.x * 64;
    const int h  = blockIdx.y;
    const int b  = blockIdx.z;
    const int tid = threadIdx.x;
    const int tx = tid & 15;
    const int ty = tid >> 4;
    const float scale = 0.08838834764831845f;

    for (int i = tid; i < 64 * 128; i += 256) {
        int r = i >> 7, c = i & 127;
        Qs[i] = Q[((size_t)(b * SEQ + q0 + r)) * DMODEL + h * DH + c];
    }

    float m[4], l[4], O[4][8];
#pragma unroll
    for (int i = 0; i < 4; i++) {
        m[i] = -1e30f; l[i] = 0.f;
#pragma unroll
        for (int j = 0; j < 8; j++) O[i][j] = 0.f;
    }
    __syncthreads();

    const int ktiles = blockIdx.x + 1;
    for (int kt = 0; kt < ktiles; ++kt) {
        const int k0 = kt * 64;
        for (int i = tid; i < 64 * 128; i += 256) {
            int r = i >> 7, c = i & 127;
            size_t row = (size_t)(b * SEQ + k0 + r);
            float kv = (c < 64) ? KV[row * KVOUT + h * KVHEAD + c]
                                : Krope[row * ROPE_D + (c - 64)];
            Ks[r * FL_KSTR + c] = kv;
            Vs[r * FL_KSTR + c] = KV[row * KVOUT + h * KVHEAD + NOPE + c];
        }
        __syncthreads();

        float sc[4][4];
#pragma unroll
        for (int i = 0; i < 4; i++)
#pragma unroll
            for (int j = 0; j < 4; j++) sc[i][j] = 0.f;

        for (int k = 0; k < 128; k += 4) {
            float4 qa[4], kb[4];
#pragma unroll
            for (int i = 0; i < 4; i++) qa[i] = *(const float4*)&Qs[(ty*4 + i)*128 + k];
#pragma unroll
            for (int j = 0; j < 4; j++) kb[j] = *(const float4*)&Ks[(tx*4 + j)*FL_KSTR + k];
#pragma unroll
            for (int i = 0; i < 4; i++)
#pragma unroll
                for (int j = 0; j < 4; j++) {
                    sc[i][j] = fmaf(qa[i].x, kb[j].x, sc[i][j]);
                    sc[i][j] = fmaf(qa[i].y, kb[j].y, sc[i][j]);
                    sc[i][j] = fmaf(qa[i].z, kb[j].z, sc[i][j]);
                    sc[i][j] = fmaf(qa[i].w, kb[j].w, sc[i][j]);
                }
        }

#pragma unroll
        for (int i = 0; i < 4; i++) {
            int qi = q0 + ty*4 + i;
            float rowmax = -1e30f;
#pragma unroll
            for (int j = 0; j < 4; j++) {
                int kj = k0 + tx*4 + j;
                sc[i][j] = (kj <= qi) ? sc[i][j] * scale : -1e30f;
                rowmax = fmaxf(rowmax, sc[i][j]);
            }
#pragma unroll
            for (int o = 1; o < 16; o <<= 1)
                rowmax = fmaxf(rowmax, __shfl_xor_sync(0xffffffffu, rowmax, o, 16));
            float mnew = fmaxf(m[i], rowmax);
            float fac  = __expf(m[i] - mnew);
            float rsum = 0.f;
#pragma unroll
            for (int j = 0; j < 4; j++) {
                float p = __expf(sc[i][j] - mnew);
                Ps[(ty*4 + i)*64 + tx*4 + j] = p;
                rsum += p;
            }
#pragma unroll
            for (int o = 1; o < 16; o <<= 1)
                rsum += __shfl_xor_sync(0xffffffffu, rsum, o, 16);
            l[i] = l[i] * fac + rsum;
            m[i] = mnew;
#pragma unroll
            for (int j = 0; j < 8; j++) O[i][j] *= fac;
        }
        __syncthreads();

        for (int kc = 0; kc < 64; kc++) {
            float4 v0 = *(const float4*)&Vs[kc*FL_KSTR + tx*8];
            float4 v1 = *(const float4*)&Vs[kc*FL_KSTR + tx*8 + 4];
#pragma unroll
            for (int i = 0; i < 4; i++) {
                float p = Ps[(ty*4 + i)*64 + kc];
                O[i][0] = fmaf(p, v0.x, O[i][0]);
                O[i][1] = fmaf(p, v0.y, O[i][1]);
                O[i][2] = fmaf(p, v0.z, O[i][2]);
                O[i][3] = fmaf(p, v0.w, O[i][3]);
                O[i][4] = fmaf(p, v1.x, O[i][4]);
                O[i][5] = fmaf(p, v1.y, O[i][5]);
                O[i][6] = fmaf(p, v1.z, O[i][6]);
                O[i][7] = fmaf(p, v1.w, O[i][7]);
            }
        }
        __syncthreads();
    }

    // epilogue: write attn_out as bf16 hi/lo (input to the W_o GEMM)
#pragma unroll
    for (int i = 0; i < 4; i++) {
        float inv = 1.f / l[i];
        size_t base = ((size_t)(b * SEQ + q0 + ty*4 + i)) * DMODEL + h * DH + tx*8;
#pragma unroll
        for (int j = 0; j < 8; j++) {
            float v = O[i][j] * inv;
            __nv_bfloat16 hh, ll;
            split_bf16(v, hh, ll);
            g_aoH[base + j] = hh;
            g_aoL[base + j] = ll;
        }
    }
}

// =====================================================================
// Launch
// =====================================================================
extern "C" void kernel_launch(void* const* d_in, const int* in_sizes, int n_in,
                              void* d_out, int out_size)
{
    const float* x       = (const float*)d_in[0];
    const float* W_dq    = (const float*)d_in[1];
    const float* W_uq    = (const float*)d_in[2];
    const float* q_ln_w  = (const float*)d_in[3];
    const float* q_ln_b  = (const float*)d_in[4];
    const float* W_dkv   = (const float*)d_in[5];
    const float* W_ukv   = (const float*)d_in[6];
    const float* kv_ln_w = (const float*)d_in[7];
    const float* kv_ln_b = (const float*)d_in[8];
    const float* W_o     = (const float*)d_in[9];

    float* out = (float*)d_out;                      // [4096, 2048]
    float* ckv = out + (size_t)MROWS * DMODEL;       // [4096, 1429]

    cudaFuncSetAttribute(flash_kernel,
                         cudaFuncAttributeMaxDynamicSharedMemorySize, FLASH_SMEM);

    dim3 tb(256), tt(32, 8);

    // ---- one-time operand preparation (split + transpose/pad) ----
    // transpose_split grid = (ceil(Npad/32), ceil(Kpad/32))
    split_rows<<<1024, 256>>>(x,   BB_XH,  BB_XL,  MROWS, DMODEL, DMODEL);
    split_rows<<<1024, 256>>>(W_o, BB_WOH, BB_WOL, DMODEL, DMODEL, DMODEL);
    transpose_split<<<dim3(32, 64), tt>>>(W_dq,  BB_WDQH,  BB_WDQL,  DMODEL, QPROJ,  DMODEL, QPROJ);
    transpose_split<<<dim3(64, 32), tt>>>(W_uq,  BB_WUQH,  BB_WUQL,  QPROJ,  DMODEL, QPROJ,  DMODEL);
    transpose_split<<<dim3(48, 64), tt>>>(W_dkv, BB_WDKVH, BB_WDKVL, DMODEL, CKV_COLS, DMODEL, WDKV_ROWS);
    transpose_split<<<dim3(96, 43), tt>>>(W_ukv, BB_WUKVH, BB_WUKVL, KVPROJ, KVOUT,  KVL_PAD, KVOUT);

    // 1) cq_pre = x @ W_dq  -> g_cq fp32
    gemm_pre<<<dim3(QPROJ/128, MROWS/128), tb>>>(
        BB_XH, BB_XL, BB_WDQH, BB_WDQL, nullptr, BUF_CQ, MROWS, QPROJ, DMODEL);
    // 2) cq = LN(cq_pre) -> bf16 hi/lo
    ln_split<<<MROWS, 256>>>(nullptr, BUF_CQ, BB_CQH, BB_CQL,
                             q_ln_w, q_ln_b, QPROJ, QPROJ, QPROJ);
    // 3) Q = cq @ W_uq -> g_Q fp32
    gemm_pre<<<dim3(DMODEL/128, MROWS/128), tb>>>(
        BB_CQH, BB_CQL, BB_WUQH, BB_WUQL, nullptr, BUF_Q, MROWS, DMODEL, QPROJ);
    // 4) RoPE(Q)
    rope_q_kernel<<<MROWS, 512>>>();
    // 5) compressed_kv = x @ W_dkv -> d_out tail (odd N, scalar epilogue)
    gemm_pre<<<dim3((CKV_COLS+127)/128, MROWS/128), tb>>>(
        BB_XH, BB_XL, BB_WDKVH, BB_WDKVL, ckv, -1, MROWS, CKV_COLS, DMODEL);
    // 6) kv_lora = LN(ckv[:, :1365]) -> bf16 hi/lo, K padded to 1376
    ln_split<<<MROWS, 256>>>(ckv, -1, BB_KVLH, BB_KVLL,
                             kv_ln_w, kv_ln_b, KVPROJ, CKV_COLS, KVL_PAD);
    // 7) K_rope = RoPE(ckv[:, 1365:])
    rope_k_kernel<<<MROWS, 32>>>(ckv);
    // 8) KV = kv_lora @ W_ukv -> g_KV fp32 (K=1376 padded, zero tail exact)
    gemm_pre<<<dim3(KVOUT/128, MROWS/128), tb>>>(
        BB_KVLH, BB_KVLL, BB_WUKVH, BB_WUKVL, nullptr, BUF_KV, MROWS, KVOUT, KVL_PAD);
    // 9) causal flash attention -> attn_out bf16 hi/lo
    flash_kernel<<<dim3(SEQ/64, NHEADS, BATCH), tb, FLASH_SMEM>>>();
    // 10) out = attn_out @ W_o^T
    gemm_pre<<<dim3(DMODEL/128, MROWS/128), tb>>>(
        BB_AOH, BB_AOL, BB_WOH, BB_WOL, out, -1, MROWS, DMODEL, DMODEL);
}

// round 17
// speedup vs baseline: 2.0205x; 2.0205x over previous
#include <cuda_runtime.h>
#include <cuda_bf16.h>
#include <math.h>
#include <stdint.h>

// ---------------- problem constants ----------------
#define SEQ     2048
#define BATCH   2
#define DMODEL  2048
#define NHEADS  16
#define DH      128
#define NOPE    64
#define ROPE_D  64
#define QPROJ   1024
#define KVPROJ  1365
#define CKV_COLS 1429          // KVPROJ + ROPE_D
#define KVOUT   3072           // NHEADS * (DH + NOPE)
#define MROWS   (BATCH*SEQ)    // 4096
#define KVHEAD  192            // DH + NOPE per head in KV
#define KVL_PAD 1376           // KVPROJ padded to a multiple of 32
#define WDKV_ROWS 1536         // CKV_COLS padded to a multiple of 128

// ---------------- fp32 scratch ----------------
__device__ float g_cq[(size_t)MROWS*QPROJ];
__device__ float g_Q[(size_t)MROWS*DMODEL];
__device__ float g_KV[(size_t)MROWS*KVOUT];
__device__ float g_Krope[(size_t)MROWS*ROPE_D];

// ---------------- bf16 hi/lo operand buffers (pre-split) ----------------
__device__ __align__(16) __nv_bfloat16 g_xH  [(size_t)MROWS*DMODEL];
__device__ __align__(16) __nv_bfloat16 g_xL  [(size_t)MROWS*DMODEL];
__device__ __align__(16) __nv_bfloat16 g_cqH [(size_t)MROWS*QPROJ];
__device__ __align__(16) __nv_bfloat16 g_cqL [(size_t)MROWS*QPROJ];
__device__ __align__(16) __nv_bfloat16 g_kvlH[(size_t)MROWS*KVL_PAD];
__device__ __align__(16) __nv_bfloat16 g_kvlL[(size_t)MROWS*KVL_PAD];
__device__ __align__(16) __nv_bfloat16 g_aoH [(size_t)MROWS*DMODEL];
__device__ __align__(16) __nv_bfloat16 g_aoL [(size_t)MROWS*DMODEL];
__device__ __align__(16) __nv_bfloat16 g_WdqH [(size_t)QPROJ*DMODEL];
__device__ __align__(16) __nv_bfloat16 g_WdqL [(size_t)QPROJ*DMODEL];
__device__ __align__(16) __nv_bfloat16 g_WuqH [(size_t)DMODEL*QPROJ];
__device__ __align__(16) __nv_bfloat16 g_WuqL [(size_t)DMODEL*QPROJ];
__device__ __align__(16) __nv_bfloat16 g_WdkvH[(size_t)WDKV_ROWS*DMODEL];
__device__ __align__(16) __nv_bfloat16 g_WdkvL[(size_t)WDKV_ROWS*DMODEL];
__device__ __align__(16) __nv_bfloat16 g_WukvH[(size_t)KVOUT*KVL_PAD];
__device__ __align__(16) __nv_bfloat16 g_WukvL[(size_t)KVOUT*KVL_PAD];
__device__ __align__(16) __nv_bfloat16 g_WoH  [(size_t)DMODEL*DMODEL];
__device__ __align__(16) __nv_bfloat16 g_WoL  [(size_t)DMODEL*DMODEL];

// fp32 buffer selectors
#define BUF_CQ 0
#define BUF_Q  1
#define BUF_KV 2
__device__ __forceinline__ float* sel_f(int s) {
    switch (s) { case BUF_CQ: return g_cq; case BUF_Q: return g_Q; default: return g_KV; }
}
// bf16 buffer selectors
#define BB_XH 0
#define BB_XL 1
#define BB_CQH 2
#define BB_CQL 3
#define BB_KVLH 4
#define BB_KVLL 5
#define BB_AOH 6
#define BB_AOL 7
#define BB_WDQH 8
#define BB_WDQL 9
#define BB_WUQH 10
#define BB_WUQL 11
#define BB_WDKVH 12
#define BB_WDKVL 13
#define BB_WUKVH 14
#define BB_WUKVL 15
#define BB_WOH 16
#define BB_WOL 17
__device__ __forceinline__ __nv_bfloat16* sel_b(int s) {
    switch (s) {
        case BB_XH: return g_xH;       case BB_XL: return g_xL;
        case BB_CQH: return g_cqH;     case BB_CQL: return g_cqL;
        case BB_KVLH: return g_kvlH;   case BB_KVLL: return g_kvlL;
        case BB_AOH: return g_aoH;     case BB_AOL: return g_aoL;
        case BB_WDQH: return g_WdqH;   case BB_WDQL: return g_WdqL;
        case BB_WUQH: return g_WuqH;   case BB_WUQL: return g_WuqL;
        case BB_WDKVH: return g_WdkvH; case BB_WDKVL: return g_WdkvL;
        case BB_WUKVH: return g_WukvH; case BB_WUKVL: return g_WukvL;
        case BB_WOH: return g_WoH;     default: return g_WoL;
    }
}

__device__ __forceinline__ void split_bf16(float v, __nv_bfloat16& h, __nv_bfloat16& l)
{
    h = __float2bfloat16(v);
    l = __float2bfloat16(v - __bfloat162float(h));
}

__device__ __forceinline__ void mma_bf16(float* c, const uint32_t* a, const uint32_t* b)
{
    asm volatile(
        "mma.sync.aligned.m16n8k16.row.col.f32.bf16.bf16.f32 "
        "{%0,%1,%2,%3}, {%4,%5,%6,%7}, {%8,%9}, {%0,%1,%2,%3};\n"
        : "+f"(c[0]), "+f"(c[1]), "+f"(c[2]), "+f"(c[3])
        : "r"(a[0]), "r"(a[1]), "r"(a[2]), "r"(a[3]), "r"(b[0]), "r"(b[1]));
}

// =====================================================================
// transpose_split: in fp32 [K][N] -> out hi/lo bf16 [Npad][Kpad], zero pad.
// grid (ceil(Npad/32), ceil(Kpad/32)), block (32, 8).
// =====================================================================
__global__ __launch_bounds__(256)
void transpose_split(const float* __restrict__ in, int selH, int selL,
                     int K, int N, int Kpad, int Npad)
{
    __shared__ float t[32][33];
    __nv_bfloat16* outH = sel_b(selH);
    __nv_bfloat16* outL = sel_b(selL);
    int x  = blockIdx.x * 32 + threadIdx.x;   // n
    int y0 = blockIdx.y * 32;                 // k base
#pragma unroll
    for (int j = threadIdx.y; j < 32; j += 8)
        t[j][threadIdx.x] = (x < N && y0 + j < K) ? in[(size_t)(y0 + j) * N + x] : 0.f;
    __syncthreads();
    int x2 = blockIdx.y * 32 + threadIdx.x;   // k
    int y2 = blockIdx.x * 32;                 // n base
#pragma unroll
    for (int j = threadIdx.y; j < 32; j += 8)
        if (x2 < Kpad && y2 + j < Npad) {
            __nv_bfloat16 h, l;
            split_bf16(t[threadIdx.x][j], h, l);
            outH[(size_t)(y2 + j) * Kpad + x2] = h;
            outL[(size_t)(y2 + j) * Kpad + x2] = l;
        }
}

// =====================================================================
// split_rows: fp32 [R][C] -> hi/lo bf16 [R][Cpad], zero pad cols.
// =====================================================================
__global__ __launch_bounds__(256)
void split_rows(const float* __restrict__ in, int selH, int selL,
                int R, int C, int Cpad)
{
    __nv_bfloat16* outH = sel_b(selH);
    __nv_bfloat16* outL = sel_b(selL);
    size_t total = (size_t)R * Cpad;
    for (size_t i = (size_t)blockIdx.x * blockDim.x + threadIdx.x; i < total;
         i += (size_t)gridDim.x * blockDim.x) {
        size_t r = i / Cpad;
        int    c = (int)(i - r * Cpad);
        float v = (c < C) ? in[r * C + c] : 0.f;
        __nv_bfloat16 h, l;
        split_bf16(v, h, l);
        outH[i] = h; outL[i] = l;
    }
}

// =====================================================================
// Pre-split bf16x3 tensor-core GEMM (NT) — unchanged (passing since R10).
// =====================================================================
#define PADK 40

__global__ __launch_bounds__(256)
void gemm_pre(int aH, int aL, int bH, int bL,
              float* __restrict__ Cext, int cSel, int M, int N, int K)
{
    const __nv_bfloat16* __restrict__ AHi = sel_b(aH);
    const __nv_bfloat16* __restrict__ ALo = sel_b(aL);
    const __nv_bfloat16* __restrict__ BHi = sel_b(bH);
    const __nv_bfloat16* __restrict__ BLo = sel_b(bL);
    float* __restrict__ C = (cSel >= 0) ? sel_f(cSel) : Cext;

    __shared__ __align__(16) __nv_bfloat16 AsHi[128 * PADK];
    __shared__ __align__(16) __nv_bfloat16 AsLo[128 * PADK];
    __shared__ __align__(16) __nv_bfloat16 BsHi[128 * PADK];
    __shared__ __align__(16) __nv_bfloat16 BsLo[128 * PADK];

    const int tid  = threadIdx.x;
    const int lane = tid & 31;
    const int warp = tid >> 5;
    const int g    = lane >> 2;
    const int tig  = lane & 3;
    const int wm   = (warp & 1) * 64;
    const int wn   = (warp >> 1) * 32;
    const int m0   = blockIdx.y * 128;
    const int n0   = blockIdx.x * 128;

    float acc[4][4][4];
#pragma unroll
    for (int mt = 0; mt < 4; mt++)
#pragma unroll
        for (int nt = 0; nt < 4; nt++)
#pragma unroll
            for (int i = 0; i < 4; i++) acc[mt][nt][i] = 0.f;

    const int nk = K >> 5;
    uint4 vAH[2], vAL[2], vBH[2], vBL[2];

    auto loadTile = [&](int kt) {
        const int k0 = kt << 5;
#pragma unroll
        for (int p = 0; p < 2; p++) {
            int lin = tid + p * 256;
            int r = lin >> 2, c8 = (lin & 3) << 3;
            size_t offA = (size_t)(m0 + r) * K + k0 + c8;
            size_t offB = (size_t)(n0 + r) * K + k0 + c8;
            vAH[p] = *(const uint4*)&AHi[offA];
            vAL[p] = *(const uint4*)&ALo[offA];
            vBH[p] = *(const uint4*)&BHi[offB];
            vBL[p] = *(const uint4*)&BLo[offB];
        }
    };

    auto storeTile = [&]() {
#pragma unroll
        for (int p = 0; p < 2; p++) {
            int lin = tid + p * 256;
            int r = lin >> 2, c8 = (lin & 3) << 3;
            int off = r * PADK + c8;
            *(uint4*)&AsHi[off] = vAH[p];
            *(uint4*)&AsLo[off] = vAL[p];
            *(uint4*)&BsHi[off] = vBH[p];
            *(uint4*)&BsLo[off] = vBL[p];
        }
    };

    loadTile(0);
    for (int kt = 0; kt < nk; kt++) {
        storeTile();
        __syncthreads();
        if (kt + 1 < nk) loadTile(kt + 1);

#pragma unroll
        for (int kk = 0; kk < 32; kk += 16) {
            uint32_t aHi[4][4], aLo[4][4], bHi[4][2], bLo[4][2];
#pragma unroll
            for (int mt = 0; mt < 4; mt++) {
                int rA = (wm + mt * 16 + g) * PADK + kk + 2 * tig;
                aHi[mt][0] = *(const uint32_t*)&AsHi[rA];
                aHi[mt][1] = *(const uint32_t*)&AsHi[rA + 8 * PADK];
                aHi[mt][2] = *(const uint32_t*)&AsHi[rA + 8];
                aHi[mt][3] = *(const uint32_t*)&AsHi[rA + 8 * PADK + 8];
                aLo[mt][0] = *(const uint32_t*)&AsLo[rA];
                aLo[mt][1] = *(const uint32_t*)&AsLo[rA + 8 * PADK];
                aLo[mt][2] = *(const uint32_t*)&AsLo[rA + 8];
                aLo[mt][3] = *(const uint32_t*)&AsLo[rA + 8 * PADK + 8];
            }
#pragma unroll
            for (int nt = 0; nt < 4; nt++) {
                int rB = (wn + nt * 8 + g) * PADK + kk + 2 * tig;
                bHi[nt][0] = *(const uint32_t*)&BsHi[rB];
                bHi[nt][1] = *(const uint32_t*)&BsHi[rB + 8];
                bLo[nt][0] = *(const uint32_t*)&BsLo[rB];
                bLo[nt][1] = *(const uint32_t*)&BsLo[rB + 8];
            }
#pragma unroll
            for (int mt = 0; mt < 4; mt++)
#pragma unroll
                for (int nt = 0; nt < 4; nt++) {
                    mma_bf16(acc[mt][nt], aHi[mt], bHi[nt]);
                    mma_bf16(acc[mt][nt], aHi[mt], bLo[nt]);
                    mma_bf16(acc[mt][nt], aLo[mt], bHi[nt]);
                }
        }
        __syncthreads();
    }

    if ((N & 1) == 0) {
#pragma unroll
        for (int mt = 0; mt < 4; mt++)
#pragma unroll
            for (int nt = 0; nt < 4; nt++) {
                int r = m0 + wm + mt * 16 + g;
                int c = n0 + wn + nt * 8 + 2 * tig;
                *(float2*)&C[(size_t)r * N + c] =
                    make_float2(acc[mt][nt][0], acc[mt][nt][1]);
                *(float2*)&C[(size_t)(r + 8) * N + c] =
                    make_float2(acc[mt][nt][2], acc[mt][nt][3]);
            }
    } else {
#pragma unroll
        for (int mt = 0; mt < 4; mt++)
#pragma unroll
            for (int nt = 0; nt < 4; nt++) {
                int r = m0 + wm + mt * 16 + g;
                int c = n0 + wn + nt * 8 + 2 * tig;
                if (c < N)     C[(size_t)r * N + c]           = acc[mt][nt][0];
                if (c + 1 < N) C[(size_t)r * N + c + 1]       = acc[mt][nt][1];
                if (c < N)     C[(size_t)(r + 8) * N + c]     = acc[mt][nt][2];
                if (c + 1 < N) C[(size_t)(r + 8) * N + c + 1] = acc[mt][nt][3];
            }
    }
}

// =====================================================================
// LayerNorm -> bf16 hi/lo pair (zero-pads cols).  Unchanged.
// =====================================================================
__global__ __launch_bounds__(256)
void ln_split(const float* __restrict__ inExt, int inSel,
              int selH, int selL,
              const float* __restrict__ w, const float* __restrict__ b,
              int cols, int in_stride, int colsPad)
{
    const float* in = (inSel >= 0) ? sel_f(inSel) : inExt;
    __nv_bfloat16* outH = sel_b(selH);
    __nv_bfloat16* outL = sel_b(selL);

    __shared__ float rs[32], rs2[32];
    const size_t row = blockIdx.x;
    const float* x = in + row * (size_t)in_stride;

    float s = 0.f, s2 = 0.f;
    for (int c = threadIdx.x; c < cols; c += blockDim.x) {
        float v = x[c]; s += v; s2 += v * v;
    }
#pragma unroll
    for (int o = 16; o; o >>= 1) {
        s  += __shfl_xor_sync(0xffffffffu, s,  o);
        s2 += __shfl_xor_sync(0xffffffffu, s2, o);
    }
    int lane = threadIdx.x & 31, wid = threadIdx.x >> 5;
    if (lane == 0) { rs[wid] = s; rs2[wid] = s2; }
    __syncthreads();
    if (wid == 0) {
        int nw = blockDim.x >> 5;
        s  = (lane < nw) ? rs[lane]  : 0.f;
        s2 = (lane < nw) ? rs2[lane] : 0.f;
#pragma unroll
        for (int o = 16; o; o >>= 1) {
            s  += __shfl_xor_sync(0xffffffffu, s,  o);
            s2 += __shfl_xor_sync(0xffffffffu, s2, o);
        }
        if (lane == 0) { rs[0] = s; rs2[0] = s2; }
    }
    __syncthreads();
    float mean = rs[0] / (float)cols;
    float var  = rs2[0] / (float)cols - mean * mean;
    float inv  = rsqrtf(var + 1e-5f);
    for (int c = threadIdx.x; c < colsPad; c += blockDim.x) {
        float y = (c < cols) ? (x[c] - mean) * inv * w[c] + b[c] : 0.f;
        __nv_bfloat16 h, l;
        split_bf16(y, h, l);
        outH[row * (size_t)colsPad + c] = h;
        outL[row * (size_t)colsPad + c] = l;
    }
}

// =====================================================================
// RoPE kernels (unchanged)
// =====================================================================
__global__ __launch_bounds__(512)
void rope_q_kernel()
{
    int bs = blockIdx.x;
    int s  = bs & (SEQ - 1);
    int h  = threadIdx.x >> 5;
    int j  = threadIdx.x & 31;
    double f   = pow(10000.0, -(double)j / 64.0);
    double ang = (double)s * f;
    double cd, sd; sincos(ang, &sd, &cd);
    float c = (float)cd, sn = (float)sd;
    float* q = g_Q + (size_t)bs * DMODEL + h * DH + NOPE;
    float x1 = q[j], x2 = q[j + 32];
    q[j]      = x1 * c - x2 * sn;
    q[j + 32] = x2 * c + x1 * sn;
}

__global__ __launch_bounds__(32)
void rope_k_kernel(const float* __restrict__ ckv)
{
    int bs = blockIdx.x;
    int s  = bs & (SEQ - 1);
    int j  = threadIdx.x;
    double f   = pow(10000.0, -(double)j / 64.0);
    double ang = (double)s * f;
    double cd, sd; sincos(ang, &sd, &cd);
    float c = (float)cd, sn = (float)sd;
    const float* src = ckv + (size_t)bs * CKV_COLS + KVPROJ;
    float x1 = src[j], x2 = src[j + 32];
    float* dst = g_Krope + (size_t)bs * ROPE_D;
    dst[j]      = x1 * c - x2 * sn;
    dst[j + 32] = x2 * c + x1 * sn;
}

// =====================================================================
// Tensor-core flash attention (causal), BM=128 q-rows, BN=64 keys, dh=128.
// 8 warps; warp w owns q-rows [w*16, w*16+16) -> softmax stats warp-local.
// S = Q K^T and O += P V both via bf16x3 mma.sync (R10-proven fragments).
// =====================================================================
#define FT_QSTR 136
#define FT_VSTR 72
#define OFF_QH  0
#define OFF_QL  (128*FT_QSTR)                  // 17408
#define OFF_KH  (2*128*FT_QSTR)                // 34816
#define OFF_KL  (OFF_KH + 64*FT_QSTR)          // 43520
#define OFF_VH  (OFF_KL + 64*FT_QSTR)          // 52224
#define OFF_VL  (OFF_VH + 128*FT_VSTR)         // 61440
#define OFF_PH  (OFF_VL + 128*FT_VSTR)         // 70656
#define OFF_PL  (OFF_PH + 128*FT_VSTR)         // 79872
#define FT_HALVES (OFF_PL + 128*FT_VSTR)       // 89088
#define FT_SMEM (FT_HALVES * 2)                // 178176 B

__global__ __launch_bounds__(256)
void flash_tc()
{
    extern __shared__ __nv_bfloat16 sb[];
    __nv_bfloat16* QsH = sb + OFF_QH;
    __nv_bfloat16* QsL = sb + OFF_QL;
    __nv_bfloat16* KsH = sb + OFF_KH;
    __nv_bfloat16* KsL = sb + OFF_KL;
    __nv_bfloat16* VtH = sb + OFF_VH;
    __nv_bfloat16* VtL = sb + OFF_VL;
    __nv_bfloat16* PsH = sb + OFF_PH;
    __nv_bfloat16* PsL = sb + OFF_PL;

    const int qb  = blockIdx.x * 128;
    const int h   = blockIdx.y;
    const int b   = blockIdx.z;
    const int tid = threadIdx.x;
    const int warp = tid >> 5;
    const int lane = tid & 31;
    const int g    = lane >> 2;
    const int tig  = lane & 3;
    const float scale = 0.08838834764831845f;   // 1/sqrt(128)

    // stage Q tile (128 x 128) hi/lo
    for (int i = tid; i < 128 * 128; i += 256) {
        int r = i >> 7, c = i & 127;
        float v = g_Q[((size_t)(b * SEQ + qb + r)) * DMODEL + h * DH + c];
        split_bf16(v, QsH[r * FT_QSTR + c], QsL[r * FT_QSTR + c]);
    }

    float O[16][4];          // nt16 over dh=128; [0..1]=row g, [2..3]=row g+8
#pragma unroll
    for (int nt = 0; nt < 16; nt++)
#pragma unroll
        for (int i = 0; i < 4; i++) O[nt][i] = 0.f;
    float mrow[2] = {-1e30f, -1e30f}, lrow[2] = {0.f, 0.f};

    const int nk = 2 * blockIdx.x + 2;
    for (int kt = 0; kt < nk; kt++) {
        const int k0 = kt * 64;
        __syncthreads();    // prior PV reads of Ks/Vt done (also covers Q stage at kt=0)
        // stage K (nope|rope) hi/lo + V transposed hi/lo
        for (int i = tid; i < 64 * 128; i += 256) {
            int r = i >> 7, c = i & 127;
            size_t row = (size_t)(b * SEQ + k0 + r);
            float kv = (c < 64) ? g_KV[row * KVOUT + h * KVHEAD + c]
                                : g_Krope[row * ROPE_D + (c - 64)];
            split_bf16(kv, KsH[r * FT_QSTR + c], KsL[r * FT_QSTR + c]);
            float vv = g_KV[row * KVOUT + h * KVHEAD + NOPE + c];
            split_bf16(vv, VtH[c * FT_VSTR + r], VtL[c * FT_VSTR + r]);
        }
        __syncthreads();

        // ---- S = Q K^T (bf16x3), warp rows = warp*16..+15 ----
        float S[8][4];
#pragma unroll
        for (int nt = 0; nt < 8; nt++)
#pragma unroll
            for (int i = 0; i < 4; i++) S[nt][i] = 0.f;

#pragma unroll
        for (int k16 = 0; k16 < 8; k16++) {
            const int kk = k16 * 16;
            uint32_t aH[4], aL[4];
            int rA = (warp * 16 + g) * FT_QSTR + kk + 2 * tig;
            aH[0] = *(const uint32_t*)&QsH[rA];
            aH[1] = *(const uint32_t*)&QsH[rA + 8 * FT_QSTR];
            aH[2] = *(const uint32_t*)&QsH[rA + 8];
            aH[3] = *(const uint32_t*)&QsH[rA + 8 * FT_QSTR + 8];
            aL[0] = *(const uint32_t*)&QsL[rA];
            aL[1] = *(const uint32_t*)&QsL[rA + 8 * FT_QSTR];
            aL[2] = *(const uint32_t*)&QsL[rA + 8];
            aL[3] = *(const uint32_t*)&QsL[rA + 8 * FT_QSTR + 8];
#pragma unroll
            for (int nt = 0; nt < 8; nt++) {
                int rB = (nt * 8 + g) * FT_QSTR + kk + 2 * tig;
                uint32_t bH[2], bL[2];
                bH[0] = *(const uint32_t*)&KsH[rB];
                bH[1] = *(const uint32_t*)&KsH[rB + 8];
                bL[0] = *(const uint32_t*)&KsL[rB];
                bL[1] = *(const uint32_t*)&KsL[rB + 8];
                mma_bf16(S[nt], aH, bH);
                mma_bf16(S[nt], aH, bL);
                mma_bf16(S[nt], aL, bH);
            }
        }

        // ---- mask + scale + online softmax (rows r0=g, r1=g+8 of warp tile) ----
        const int r0 = qb + warp * 16 + g;
        const int r1 = r0 + 8;
        float mnew0 = mrow[0], mnew1 = mrow[1];
#pragma unroll
        for (int nt = 0; nt < 8; nt++) {
            int c0 = k0 + nt * 8 + 2 * tig;
            S[nt][0] = (c0     <= r0) ? S[nt][0] * scale : -1e30f;
            S[nt][1] = (c0 + 1 <= r0) ? S[nt][1] * scale : -1e30f;
            S[nt][2] = (c0     <= r1) ? S[nt][2] * scale : -1e30f;
            S[nt][3] = (c0 + 1 <= r1) ? S[nt][3] * scale : -1e30f;
            mnew0 = fmaxf(mnew0, fmaxf(S[nt][0], S[nt][1]));
            mnew1 = fmaxf(mnew1, fmaxf(S[nt][2], S[nt][3]));
        }
#pragma unroll
        for (int o = 1; o < 4; o <<= 1) {
            mnew0 = fmaxf(mnew0, __shfl_xor_sync(0xffffffffu, mnew0, o));
            mnew1 = fmaxf(mnew1, __shfl_xor_sync(0xffffffffu, mnew1, o));
        }
        float fac0 = __expf(mrow[0] - mnew0);
        float fac1 = __expf(mrow[1] - mnew1);
        mrow[0] = mnew0; mrow[1] = mnew1;
        float sum0 = 0.f, sum1 = 0.f;
        const int prow0 = (warp * 16 + g) * FT_VSTR;
        const int prow1 = prow0 + 8 * FT_VSTR;
#pragma unroll
        for (int nt = 0; nt < 8; nt++) {
            float p0 = __expf(S[nt][0] - mnew0);
            float p1 = __expf(S[nt][1] - mnew0);
            float p2 = __expf(S[nt][2] - mnew1);
            float p3 = __expf(S[nt][3] - mnew1);
            sum0 += p0 + p1; sum1 += p2 + p3;
            __nv_bfloat16 h0, l0, h1, l1;
            int cc = nt * 8 + 2 * tig;
            split_bf16(p0, h0, l0); split_bf16(p1, h1, l1);
            *(uint32_t*)&PsH[prow0 + cc] = ((uint32_t)*(uint16_t*)&h1 << 16) | *(uint16_t*)&h0;
            *(uint32_t*)&PsL[prow0 + cc] = ((uint32_t)*(uint16_t*)&l1 << 16) | *(uint16_t*)&l0;
            split_bf16(p2, h0, l0); split_bf16(p3, h1, l1);
            *(uint32_t*)&PsH[prow1 + cc] = ((uint32_t)*(uint16_t*)&h1 << 16) | *(uint16_t*)&h0;
            *(uint32_t*)&PsL[prow1 + cc] = ((uint32_t)*(uint16_t*)&l1 << 16) | *(uint16_t*)&l0;
        }
#pragma unroll
        for (int o = 1; o < 4; o <<= 1) {
            sum0 += __shfl_xor_sync(0xffffffffu, sum0, o);
            sum1 += __shfl_xor_sync(0xffffffffu, sum1, o);
        }
        lrow[0] = lrow[0] * fac0 + sum0;
        lrow[1] = lrow[1] * fac1 + sum1;
#pragma unroll
        for (int nt = 0; nt < 16; nt++) {
            O[nt][0] *= fac0; O[nt][1] *= fac0;
            O[nt][2] *= fac1; O[nt][3] *= fac1;
        }
        __syncwarp();   // P visible to own warp

        // ---- O += P V (bf16x3): A = P rows of warp, B = Vt[d][kc] ----
#pragma unroll
        for (int k16 = 0; k16 < 4; k16++) {
            const int kk = k16 * 16;
            uint32_t aH[4], aL[4];
            int rA = (warp * 16 + g) * FT_VSTR + kk + 2 * tig;
            aH[0] = *(const uint32_t*)&PsH[rA];
            aH[1] = *(const uint32_t*)&PsH[rA + 8 * FT_VSTR];
            aH[2] = *(const uint32_t*)&PsH[rA + 8];
            aH[3] = *(const uint32_t*)&PsH[rA + 8 * FT_VSTR + 8];
            aL[0] = *(const uint32_t*)&PsL[rA];
            aL[1] = *(const uint32_t*)&PsL[rA + 8 * FT_VSTR];
            aL[2] = *(const uint32_t*)&PsL[rA + 8];
            aL[3] = *(const uint32_t*)&PsL[rA + 8 * FT_VSTR + 8];
#pragma unroll
            for (int nt = 0; nt < 16; nt++) {
                int rB = (nt * 8 + g) * FT_VSTR + kk + 2 * tig;
                uint32_t bH[2], bL[2];
                bH[0] = *(const uint32_t*)&VtH[rB];
                bH[1] = *(const uint32_t*)&VtH[rB + 8];
                bL[0] = *(const uint32_t*)&VtL[rB];
                bL[1] = *(const uint32_t*)&VtL[rB + 8];
                mma_bf16(O[nt], aH, bH);
                mma_bf16(O[nt], aH, bL);
                mma_bf16(O[nt], aL, bH);
            }
        }
    }

    // ---- epilogue: attn_out = O / l as bf16 hi/lo ----
    float inv0 = 1.f / lrow[0], inv1 = 1.f / lrow[1];
    size_t base0 = ((size_t)(b * SEQ + qb + warp * 16 + g)) * DMODEL + h * DH;
    size_t base1 = base0 + 8 * DMODEL;
#pragma unroll
    for (int nt = 0; nt < 16; nt++) {
        int c = nt * 8 + 2 * tig;
        __nv_bfloat16 hh, ll;
        split_bf16(O[nt][0] * inv0, hh, ll); g_aoH[base0 + c]     = hh; g_aoL[base0 + c]     = ll;
        split_bf16(O[nt][1] * inv0, hh, ll); g_aoH[base0 + c + 1] = hh; g_aoL[base0 + c + 1] = ll;
        split_bf16(O[nt][2] * inv1, hh, ll); g_aoH[base1 + c]     = hh; g_aoL[base1 + c]     = ll;
        split_bf16(O[nt][3] * inv1, hh, ll); g_aoH[base1 + c + 1] = hh; g_aoL[base1 + c + 1] = ll;
    }
}

// =====================================================================
// Launch
// =====================================================================
extern "C" void kernel_launch(void* const* d_in, const int* in_sizes, int n_in,
                              void* d_out, int out_size)
{
    const float* x       = (const float*)d_in[0];
    const float* W_dq    = (const float*)d_in[1];
    const float* W_uq    = (const float*)d_in[2];
    const float* q_ln_w  = (const float*)d_in[3];
    const float* q_ln_b  = (const float*)d_in[4];
    const float* W_dkv   = (const float*)d_in[5];
    const float* W_ukv   = (const float*)d_in[6];
    const float* kv_ln_w = (const float*)d_in[7];
    const float* kv_ln_b = (const float*)d_in[8];
    const float* W_o     = (const float*)d_in[9];

    float* out = (float*)d_out;                      // [4096, 2048]
    float* ckv = out + (size_t)MROWS * DMODEL;       // [4096, 1429]

    cudaFuncSetAttribute(flash_tc,
                         cudaFuncAttributeMaxDynamicSharedMemorySize, FT_SMEM);

    dim3 tb(256), tt(32, 8);

    // ---- one-time operand preparation ----
    // transpose_split grid = (ceil(Npad/32), ceil(Kpad/32))
    split_rows<<<1024, 256>>>(x,   BB_XH,  BB_XL,  MROWS, DMODEL, DMODEL);
    split_rows<<<1024, 256>>>(W_o, BB_WOH, BB_WOL, DMODEL, DMODEL, DMODEL);
    transpose_split<<<dim3(32, 64), tt>>>(W_dq,  BB_WDQH,  BB_WDQL,  DMODEL, QPROJ,  DMODEL, QPROJ);
    transpose_split<<<dim3(64, 32), tt>>>(W_uq,  BB_WUQH,  BB_WUQL,  QPROJ,  DMODEL, QPROJ,  DMODEL);
    transpose_split<<<dim3(48, 64), tt>>>(W_dkv, BB_WDKVH, BB_WDKVL, DMODEL, CKV_COLS, DMODEL, WDKV_ROWS);
    transpose_split<<<dim3(96, 43), tt>>>(W_ukv, BB_WUKVH, BB_WUKVL, KVPROJ, KVOUT,  KVL_PAD, KVOUT);

    // 1) cq_pre = x @ W_dq  -> g_cq fp32
    gemm_pre<<<dim3(QPROJ/128, MROWS/128), tb>>>(
        BB_XH, BB_XL, BB_WDQH, BB_WDQL, nullptr, BUF_CQ, MROWS, QPROJ, DMODEL);
    // 2) cq = LN(cq_pre) -> bf16 hi/lo
    ln_split<<<MROWS, 256>>>(nullptr, BUF_CQ, BB_CQH, BB_CQL,
                             q_ln_w, q_ln_b, QPROJ, QPROJ, QPROJ);
    // 3) Q = cq @ W_uq -> g_Q fp32
    gemm_pre<<<dim3(DMODEL/128, MROWS/128), tb>>>(
        BB_CQH, BB_CQL, BB_WUQH, BB_WUQL, nullptr, BUF_Q, MROWS, DMODEL, QPROJ);
    // 4) RoPE(Q)
    rope_q_kernel<<<MROWS, 512>>>();
    // 5) compressed_kv = x @ W_dkv -> d_out tail (odd N, scalar epilogue)
    gemm_pre<<<dim3((CKV_COLS+127)/128, MROWS/128), tb>>>(
        BB_XH, BB_XL, BB_WDKVH, BB_WDKVL, ckv, -1, MROWS, CKV_COLS, DMODEL);
    // 6) kv_lora = LN(ckv[:, :1365]) -> bf16 hi/lo, K padded to 1376
    ln_split<<<MROWS, 256>>>(ckv, -1, BB_KVLH, BB_KVLL,
                             kv_ln_w, kv_ln_b, KVPROJ, CKV_COLS, KVL_PAD);
    // 7) K_rope = RoPE(ckv[:, 1365:])
    rope_k_kernel<<<MROWS, 32>>>(ckv);
    // 8) KV = kv_lora @ W_ukv -> g_KV fp32 (K=1376 padded, zero tail exact)
    gemm_pre<<<dim3(KVOUT/128, MROWS/128), tb>>>(
        BB_KVLH, BB_KVLL, BB_WUKVH, BB_WUKVL, nullptr, BUF_KV, MROWS, KVOUT, KVL_PAD);
    // 9) tensor-core causal flash attention -> attn_out bf16 hi/lo
    flash_tc<<<dim3(SEQ/128, NHEADS, BATCH), tb, FT_SMEM>>>();
    // 10) out = attn_out @ W_o^T
    gemm_pre<<<dim3(DMODEL/128, MROWS/128), tb>>>(
        BB_AOH, BB_AOL, BB_WOH, BB_WOL, out, -1, MROWS, DMODEL, DMODEL);
}